// round 17
// baseline (speedup 1.0000x reference)
#include <cuda_runtime.h>
#include <cuda_fp16.h>
#include <math.h>

// ---------------------------------------------------------------------------
// Instant-NGP multires hash-grid encoding, R17.
//   = R14 tables (dense 0-4, E shadow + B1 for 5-15) with the main kernel
//   made BRANCHLESS around memory: every lane computes ONE uint2 index into
//   g_mem for each of its 4 corner pairs (dense / E-even / B1 / E-floor),
//   then a single fully-active group of 4x LDG.64 issues, plus 4x LDG.32
//   under a ~25%-active predicate (hash fx%4==3 ceil corners).
//   R12-R16 kernels serialized up to 4 divergent load groups per warp
//   (dense lanes + 3 hash fx-classes); this removes that issue overhead.
//
// SCALINGS hardcoded; level 15 = 4095 (proven by R13 failure signature).
// ---------------------------------------------------------------------------

#define NUM_LEVELS 16
#define LOG2_T     19
#define T_CONST    (1u << LOG2_T)
#define T_MASK     (T_CONST - 1u)
#define TAB_ENTRIES (1u << 23)        // 16*T unsigned
#define N_DENSE_LEVELS 5
#define HASH_LEVELS 11
#define DENSE_TOTAL 533601            // 17^3+24^3+34^3+49^3+71^3
#define B1_BASE TAB_ENTRIES           // unsigned offset of B1 region
#define B1_BASE_U2 (TAB_ENTRIES / 2)  // same, in uint2 units

__device__ unsigned g_mem[TAB_ENTRIES + 2u * (HASH_LEVELS << LOG2_T)];  // 80MB

// floor(16 * growth^l) per numpy's float64 chain. Level 15 = 4095 (NOT 4096).
__constant__ float c_scale[NUM_LEVELS] = {
    16.f, 23.f, 33.f, 48.f, 70.f, 101.f, 147.f, 212.f,
    307.f, 445.f, 645.f, 933.f, 1351.f, 1955.f, 2830.f, 4095.f
};

__constant__ int c_denseR[N_DENSE_LEVELS]   = {17, 24, 34, 49, 71};
__constant__ int c_denseOff[N_DENSE_LEVELS] = {0, 4913, 18737, 58041, 175690};

// Fused prep for hash levels 5..15 (R14 variant — best measured at 23.8us):
// f32 -> half2 E shadow AND B1 pair table; one thread per 4-entry group.
__global__ __launch_bounds__(256) void build_shadow_kernel(const float4* __restrict__ src) {
    unsigned i = blockIdx.x * blockDim.x + threadIdx.x;   // < 11 * T/4
    unsigned lvl5 = i >> 17;                               // T/4 = 131072
    unsigned g    = i & 131071u;

    unsigned e0 = (lvl5 + 5u) * T_CONST + 4u * g;          // absolute entry
    const float4* s4 = src + (e0 >> 1);

    float4 w0 = __ldg(s4 + 0);
    float4 w1 = __ldg(s4 + 1);

    unsigned v[4];
    {
        __half2 a;
        a = __floats2half2_rn(w0.x, w0.y); v[0] = *reinterpret_cast<unsigned*>(&a);
        a = __floats2half2_rn(w0.z, w0.w); v[1] = *reinterpret_cast<unsigned*>(&a);
        a = __floats2half2_rn(w1.x, w1.y); v[2] = *reinterpret_cast<unsigned*>(&a);
        a = __floats2half2_rn(w1.z, w1.w); v[3] = *reinterpret_cast<unsigned*>(&a);
    }

    // E shadow: 4 consecutive half2 entries = 16B
    *reinterpret_cast<uint4*>(g_mem + e0) = make_uint4(v[0], v[1], v[2], v[3]);

    // B1 (level-local): B1[h] = (v[h], v[h^3]); two pairs per uint4 store.
    unsigned bb = lvl5 * T_CONST + 4u * g;
    uint4* bp = reinterpret_cast<uint4*>(reinterpret_cast<uint2*>(g_mem + B1_BASE) + bb);
    bp[0] = make_uint4(v[0], v[3], v[1], v[2]);   // B1[0], B1[1]
    bp[1] = make_uint4(v[2], v[1], v[3], v[0]);   // B1[2], B1[3]
}

// Dense pair tables for levels 0..4 in the dead front of g_mem (entries < 5T).
__global__ __launch_bounds__(256) void dense_fill_kernel(const float2* __restrict__ src) {
    int e = blockIdx.x * blockDim.x + threadIdx.x;
    if (e >= DENSE_TOTAL) return;

    int l = 0;
    #pragma unroll
    for (int i = 1; i < N_DENSE_LEVELS; i++)
        if (e >= c_denseOff[i]) l = i;

    int r = e - c_denseOff[l];
    int R = c_denseR[l];
    int z = r / (R * R);
    int rem = r - z * R * R;
    int y = rem / R;
    int x = rem - y * R;

    unsigned h = ((unsigned)x ^ ((unsigned)y * 2654435761u) ^ ((unsigned)z * 805459861u)) & T_MASK;
    h += (unsigned)l << LOG2_T;

    float2 fv = __ldg(src + h);
    __half2 hv = __floats2half2_rn(fv.x, fv.y);
    unsigned v = *reinterpret_cast<unsigned*>(&hv);

    g_mem[2 * e] = v;                 // pair[e].x  (floor-x corner)
    if (x > 0) g_mem[2 * e - 1] = v;  // pair[e-1].y (ceil-x corner of prev)
}

__device__ __forceinline__ float2 h2f(unsigned bits) {
    __half2 h = *reinterpret_cast<__half2*>(&bits);
    return __half22float2(h);
}

__global__ __launch_bounds__(256) void hashgrid_kernel(
    const float*  __restrict__ pts,   // [npts, 3]
    float2*       __restrict__ out,   // [npts, 16] float2
    int npts)
{
    int t = blockIdx.x * blockDim.x + threadIdx.x;
    int p = t >> 4;
    int l = t & (NUM_LEVELS - 1);
    if (p >= npts) return;

    float x = __ldcs(pts + 3 * p + 0);
    float y = __ldcs(pts + 3 * p + 1);
    float z = __ldcs(pts + 3 * p + 2);

    float s = c_scale[l];
    float sx = x * s, sy = y * s, sz = z * s;

    float fxf = floorf(sx), fyf = floorf(sy), fzf = floorf(sz);
    float ox = sx - fxf, oy = sy - fyf, oz = sz - fzf;

    int fx = (int)fxf,       fy = (int)fyf,       fz = (int)fzf;
    int cx = (int)ceilf(sx), cy = (int)ceilf(sy), cz = (int)ceilf(sz);

    // ---- per-pair uint2 index computation (ALU only, no loads) ----
    unsigned pi03, pi12, pi56, pi47;       // uint2-unit indices into g_mem
    unsigned sel03, sel12, sel56, sel47;   // 1 -> floor corner is hi half
    bool     extra;                        // hash fx%4==3: ceil needs 4B load
    unsigned ei03 = 0, ei12 = 0, ei56 = 0, ei47 = 0;  // extra element indices

    if (l < N_DENSE_LEVELS) {
        int R  = c_denseR[l];
        int R2 = R * R;
        int off = c_denseOff[l];
        pi03 = off + fx + cy * R + cz * R2;
        pi12 = off + fx + fy * R + cz * R2;
        pi56 = off + fx + fy * R + fz * R2;
        pi47 = off + fx + cy * R + fz * R2;
        sel03 = sel12 = sel56 = sel47 = 0u;
        extra = false;
    } else {
        unsigned hcy = (unsigned)cy * 2654435761u;
        unsigned hfy = (unsigned)fy * 2654435761u;
        unsigned hcz = (unsigned)cz * 805459861u;
        unsigned hfz = (unsigned)fz * 805459861u;

        unsigned r03 = hcy ^ hcz;
        unsigned r12 = hfy ^ hcz;
        unsigned r56 = hfy ^ hfz;
        unsigned r47 = hcy ^ hfz;

        unsigned ufx = (unsigned)fx;
        unsigned loc03 = (ufx ^ r03) & T_MASK;
        unsigned loc12 = (ufx ^ r12) & T_MASK;
        unsigned loc56 = (ufx ^ r56) & T_MASK;
        unsigned loc47 = (ufx ^ r47) & T_MASK;

        unsigned lbase = (unsigned)l << LOG2_T;

        if ((fx & 3) == 1) {
            // B1 pair: (v[loc], v[loc^3]) at B1_BASE_U2 + level-local index.
            unsigned bb = B1_BASE_U2 + ((unsigned)(l - 5) << LOG2_T);
            pi03 = bb + loc03;
            pi12 = bb + loc12;
            pi56 = bb + loc56;
            pi47 = bb + loc47;
            sel03 = sel12 = sel56 = sel47 = 0u;
            extra = false;
        } else {
            // E natural pair holds the floor corner (and the ceil corner
            // too when fx is even).
            pi03 = (lbase + loc03) >> 1;
            pi12 = (lbase + loc12) >> 1;
            pi56 = (lbase + loc56) >> 1;
            pi47 = (lbase + loc47) >> 1;
            sel03 = loc03 & 1u;
            sel12 = loc12 & 1u;
            sel56 = loc56 & 1u;
            sel47 = loc47 & 1u;
            extra = (fx & 1);   // fx%4==3: ceil corner from its own entry
            if (extra) {
                unsigned ucx = (unsigned)cx;
                ei03 = lbase + ((ucx ^ r03) & T_MASK);
                ei12 = lbase + ((ucx ^ r12) & T_MASK);
                ei56 = lbase + ((ucx ^ r56) & T_MASK);
                ei47 = lbase + ((ucx ^ r47) & T_MASK);
            }
        }
    }

    // ---- unified loads: 4x LDG.64 fully active, 4x LDG.32 predicated ----
    const uint2* gp = reinterpret_cast<const uint2*>(g_mem);
    uint2 P03 = __ldg(gp + pi03);
    uint2 P12 = __ldg(gp + pi12);
    uint2 P56 = __ldg(gp + pi56);
    uint2 P47 = __ldg(gp + pi47);

    unsigned E03 = 0, E12 = 0, E56 = 0, E47 = 0;
    if (extra) {
        E03 = __ldg(g_mem + ei03);
        E12 = __ldg(g_mem + ei12);
        E56 = __ldg(g_mem + ei56);
        E47 = __ldg(g_mem + ei47);
    }

    // ---- unified selection ----
    unsigned vf03 = sel03 ? P03.y : P03.x;
    unsigned vf12 = sel12 ? P12.y : P12.x;
    unsigned vf56 = sel56 ? P56.y : P56.x;
    unsigned vf47 = sel47 ? P47.y : P47.x;
    unsigned vc03 = extra ? E03 : (sel03 ? P03.x : P03.y);
    unsigned vc12 = extra ? E12 : (sel12 ? P12.x : P12.y);
    unsigned vc56 = extra ? E56 : (sel56 ? P56.x : P56.y);
    unsigned vc47 = extra ? E47 : (sel47 ? P47.x : P47.y);
    // Exact-integer sx (cx==fx): wrong ceil value but weight ox == 0.

    float2 f0 = h2f(vc03), f3 = h2f(vf03);
    float2 f1 = h2f(vc12), f2 = h2f(vf12);
    float2 f5 = h2f(vc56), f6 = h2f(vf56);
    float2 f4 = h2f(vc47), f7 = h2f(vf47);

    float mx = 1.0f - ox, my = 1.0f - oy, mz = 1.0f - oz;

    // x-lerp (ceil-x corner weighted by ox, per reference)
    float a03x = f0.x * ox + f3.x * mx;
    float a03y = f0.y * ox + f3.y * mx;
    float a12x = f1.x * ox + f2.x * mx;
    float a12y = f1.y * ox + f2.y * mx;
    float a56x = f5.x * ox + f6.x * mx;
    float a56y = f5.y * ox + f6.y * mx;
    float a47x = f4.x * ox + f7.x * mx;
    float a47y = f4.y * ox + f7.y * mx;

    // y-lerp
    float bx = a03x * oy + a12x * my;
    float by = a03y * oy + a12y * my;
    float gx = a47x * oy + a56x * my;
    float gy = a47y * oy + a56y * my;

    // z-lerp
    float2 e;
    e.x = bx * oz + gx * mz;
    e.y = by * oz + gy * mz;

    __stcs(&out[(size_t)p * NUM_LEVELS + l], e);
}

extern "C" void kernel_launch(void* const* d_in, const int* in_sizes, int n_in,
                              void* d_out, int out_size) {
    const float* pts = (const float*)d_in[0];
    const float* tab = (const float*)d_in[1];
    float2*      out = (float2*)d_out;

    int npts = in_sizes[0] / 3;

    // Hash levels 5..15: E shadow + B1 pair table (one thread / 4 entries).
    unsigned groups = HASH_LEVELS * (T_CONST / 4u);
    build_shadow_kernel<<<groups / 256, 256>>>((const float4*)tab);

    // Dense pair tables for levels 0..4 (front of g_mem).
    dense_fill_kernel<<<(DENSE_TOTAL + 255) / 256, 256>>>((const float2*)tab);

    long long total = (long long)npts * NUM_LEVELS;
    int threads = 256;
    int blocks = (int)((total + threads - 1) / threads);
    hashgrid_kernel<<<blocks, threads>>>(pts, out, npts);
}